// round 1
// baseline (speedup 1.0000x reference)
#include <cuda_runtime.h>
#include <cuda_bf16.h>
#include <math.h>

#define NPTS 8192
#define BATCH 4
#define K 16
#define TILE 2048
#define TPB 128

__global__ __launch_bounds__(TPB)
void eig_ratio_kernel(const float* __restrict__ x, float* __restrict__ out) {
    __shared__ float4 tile[TILE];  // xyz + |p|^2, 32 KB

    const int b = blockIdx.y;
    const int q = blockIdx.x * TPB + threadIdx.x;
    const float* P = x + (size_t)b * NPTS * 3;

    const float qx = P[q * 3 + 0];
    const float qy = P[q * 3 + 1];
    const float qz = P[q * 3 + 2];
    const float qsq = qx * qx + qy * qy + qz * qz;

    float bval[K];
    int   bidx[K];
#pragma unroll
    for (int t = 0; t < K; t++) { bval[t] = 3.4e38f; bidx[t] = 0; }
    float worst = 3.4e38f;

    for (int t0 = 0; t0 < NPTS; t0 += TILE) {
        __syncthreads();
        for (int i = threadIdx.x; i < TILE; i += TPB) {
            const float px = P[(t0 + i) * 3 + 0];
            const float py = P[(t0 + i) * 3 + 1];
            const float pz = P[(t0 + i) * 3 + 2];
            tile[i] = make_float4(px, py, pz, px * px + py * py + pz * pz);
        }
        __syncthreads();

#pragma unroll 4
        for (int j = 0; j < TILE; j++) {
            const float4 c = tile[j];
            const float dot = qx * c.x + qy * c.y + qz * c.z;
            const float d2 = (qsq + c.w) - 2.0f * dot;
            if (d2 < worst) {
                // replace current max of the 16-best set
                int ms = 0;
                float mv = bval[0];
#pragma unroll
                for (int t = 1; t < K; t++)
                    if (bval[t] > mv) { mv = bval[t]; ms = t; }
#pragma unroll
                for (int t = 0; t < K; t++)
                    if (t == ms) { bval[t] = d2; bidx[t] = t0 + j; }
                worst = bval[0];
#pragma unroll
                for (int t = 1; t < K; t++) worst = fmaxf(worst, bval[t]);
            }
        }
    }

    // ---- epilogue: gather neighbors, covariance (fp32, mimic reference) ----
    float nx[K], ny[K], nz[K];
#pragma unroll
    for (int t = 0; t < K; t++) {
        const int id = bidx[t];
        nx[t] = P[id * 3 + 0];
        ny[t] = P[id * 3 + 1];
        nz[t] = P[id * 3 + 2];
    }
    float mx = 0.f, my = 0.f, mz = 0.f;
#pragma unroll
    for (int t = 0; t < K; t++) { mx += nx[t]; my += ny[t]; mz += nz[t]; }
    const float invk = 1.0f / (float)K;
    mx *= invk; my *= invk; mz *= invk;

    float c00 = 0.f, c01 = 0.f, c02 = 0.f, c11 = 0.f, c12 = 0.f, c22 = 0.f;
#pragma unroll
    for (int t = 0; t < K; t++) {
        const float dx = nx[t] - mx, dy = ny[t] - my, dz = nz[t] - mz;
        c00 += dx * dx; c01 += dx * dy; c02 += dx * dz;
        c11 += dy * dy; c12 += dy * dz; c22 += dz * dz;
    }

    // ---- 3x3 symmetric eigenvalues, trigonometric closed form (fp64) ----
    const double a00 = (double)(c00 * invk);
    const double a01 = (double)(c01 * invk);
    const double a02 = (double)(c02 * invk);
    const double a11 = (double)(c11 * invk);
    const double a12 = (double)(c12 * invk);
    const double a22 = (double)(c22 * invk);

    const double qm = (a00 + a11 + a22) / 3.0;
    const double p1 = a01 * a01 + a02 * a02 + a12 * a12;
    const double d0 = a00 - qm, d1 = a11 - qm, d2e = a22 - qm;
    const double p2 = d0 * d0 + d1 * d1 + d2e * d2e + 2.0 * p1;

    double ratio;
    if (p2 <= 0.0) {
        ratio = 1.0;  // isotropic: all eigenvalues equal
    } else {
        const double pp  = sqrt(p2 / 6.0);
        const double inv = 1.0 / pp;
        const double b00 = d0 * inv, b11 = d1 * inv, b22 = d2e * inv;
        const double b01 = a01 * inv, b02 = a02 * inv, b12 = a12 * inv;
        const double detB = b00 * (b11 * b22 - b12 * b12)
                          - b01 * (b01 * b22 - b12 * b02)
                          + b02 * (b01 * b12 - b11 * b02);
        double r = 0.5 * detB;
        r = fmin(1.0, fmax(-1.0, r));
        const double phi = acos(r) / 3.0;
        const double e_big   = qm + 2.0 * pp * cos(phi);                       // largest
        const double e_small = qm + 2.0 * pp * cos(phi + 2.0943951023931953);  // smallest
        const double e_mid   = 3.0 * qm - e_big - e_small;                     // middle
        ratio = e_big / e_mid;
    }

    out[(size_t)b * NPTS + q] = (float)ratio;
}

extern "C" void kernel_launch(void* const* d_in, const int* in_sizes, int n_in,
                              void* d_out, int out_size) {
    const float* x = (const float*)d_in[0];   // (4, 8192, 3) fp32
    float* out = (float*)d_out;               // (4, 8192) fp32
    dim3 grid(NPTS / TPB, BATCH);
    eig_ratio_kernel<<<grid, TPB>>>(x, out);
}

// round 2
// speedup vs baseline: 1.0015x; 1.0015x over previous
#include <cuda_runtime.h>
#include <cuda_bf16.h>
#include <math.h>

#define NPTS 8192
#define BATCH 4
#define K 16
#define TILE 2048
#define TPB 128

__global__ __launch_bounds__(TPB)
void eig_ratio_kernel(const float* __restrict__ x, float* __restrict__ out) {
    __shared__ float4 tile[TILE];  // xyz + |p|^2, 32 KB

    const int b = blockIdx.y;
    const int q = blockIdx.x * TPB + threadIdx.x;
    const float* P = x + (size_t)b * NPTS * 3;

    const float qx = P[q * 3 + 0];
    const float qy = P[q * 3 + 1];
    const float qz = P[q * 3 + 2];
    const float qsq = qx * qx + qy * qy + qz * qz;

    float bval[K];
    int   bidx[K];
#pragma unroll
    for (int t = 0; t < K; t++) { bval[t] = 3.4e38f; bidx[t] = 0; }
    float worst = 3.4e38f;

    for (int t0 = 0; t0 < NPTS; t0 += TILE) {
        __syncthreads();
        for (int i = threadIdx.x; i < TILE; i += TPB) {
            const float px = P[(t0 + i) * 3 + 0];
            const float py = P[(t0 + i) * 3 + 1];
            const float pz = P[(t0 + i) * 3 + 2];
            tile[i] = make_float4(px, py, pz, px * px + py * py + pz * pz);
        }
        __syncthreads();

#pragma unroll 4
        for (int j = 0; j < TILE; j++) {
            const float4 c = tile[j];
            const float dot = qx * c.x + qy * c.y + qz * c.z;
            const float d2 = (qsq + c.w) - 2.0f * dot;
            if (d2 < worst) {
                // replace current max of the 16-best set
                int ms = 0;
                float mv = bval[0];
#pragma unroll
                for (int t = 1; t < K; t++)
                    if (bval[t] > mv) { mv = bval[t]; ms = t; }
#pragma unroll
                for (int t = 0; t < K; t++)
                    if (t == ms) { bval[t] = d2; bidx[t] = t0 + j; }
                worst = bval[0];
#pragma unroll
                for (int t = 1; t < K; t++) worst = fmaxf(worst, bval[t]);
            }
        }
    }

    // ---- epilogue: gather neighbors, covariance (fp32, mimic reference) ----
    float nx[K], ny[K], nz[K];
#pragma unroll
    for (int t = 0; t < K; t++) {
        const int id = bidx[t];
        nx[t] = P[id * 3 + 0];
        ny[t] = P[id * 3 + 1];
        nz[t] = P[id * 3 + 2];
    }
    float mx = 0.f, my = 0.f, mz = 0.f;
#pragma unroll
    for (int t = 0; t < K; t++) { mx += nx[t]; my += ny[t]; mz += nz[t]; }
    const float invk = 1.0f / (float)K;
    mx *= invk; my *= invk; mz *= invk;

    float c00 = 0.f, c01 = 0.f, c02 = 0.f, c11 = 0.f, c12 = 0.f, c22 = 0.f;
#pragma unroll
    for (int t = 0; t < K; t++) {
        const float dx = nx[t] - mx, dy = ny[t] - my, dz = nz[t] - mz;
        c00 += dx * dx; c01 += dx * dy; c02 += dx * dz;
        c11 += dy * dy; c12 += dy * dz; c22 += dz * dz;
    }

    // ---- 3x3 symmetric eigenvalues, trigonometric closed form (fp64) ----
    const double a00 = (double)(c00 * invk);
    const double a01 = (double)(c01 * invk);
    const double a02 = (double)(c02 * invk);
    const double a11 = (double)(c11 * invk);
    const double a12 = (double)(c12 * invk);
    const double a22 = (double)(c22 * invk);

    const double qm = (a00 + a11 + a22) / 3.0;
    const double p1 = a01 * a01 + a02 * a02 + a12 * a12;
    const double d0 = a00 - qm, d1 = a11 - qm, d2e = a22 - qm;
    const double p2 = d0 * d0 + d1 * d1 + d2e * d2e + 2.0 * p1;

    double ratio;
    if (p2 <= 0.0) {
        ratio = 1.0;  // isotropic: all eigenvalues equal
    } else {
        const double pp  = sqrt(p2 / 6.0);
        const double inv = 1.0 / pp;
        const double b00 = d0 * inv, b11 = d1 * inv, b22 = d2e * inv;
        const double b01 = a01 * inv, b02 = a02 * inv, b12 = a12 * inv;
        const double detB = b00 * (b11 * b22 - b12 * b12)
                          - b01 * (b01 * b22 - b12 * b02)
                          + b02 * (b01 * b12 - b11 * b02);
        double r = 0.5 * detB;
        r = fmin(1.0, fmax(-1.0, r));
        const double phi = acos(r) / 3.0;
        const double e_big   = qm + 2.0 * pp * cos(phi);                       // largest
        const double e_small = qm + 2.0 * pp * cos(phi + 2.0943951023931953);  // smallest
        const double e_mid   = 3.0 * qm - e_big - e_small;                     // middle
        ratio = e_big / e_mid;
    }

    out[(size_t)b * NPTS + q] = (float)ratio;
}

extern "C" void kernel_launch(void* const* d_in, const int* in_sizes, int n_in,
                              void* d_out, int out_size) {
    const float* x = (const float*)d_in[0];   // (4, 8192, 3) fp32
    float* out = (float*)d_out;               // (4, 8192) fp32
    dim3 grid(NPTS / TPB, BATCH);
    eig_ratio_kernel<<<grid, TPB>>>(x, out);
}